// round 15
// baseline (speedup 1.0000x reference)
#include <cuda_runtime.h>
#include <math.h>

#define TPB 128
#define RSTR 52                 // row stride in floats (13 vec4): 20l%32 distinct -> LDS.128 conflict-free
#define NEG_INF (-3.402823466e+38f)
#define LOG2E 1.4426950408889634f

__device__ __forceinline__ float ex2(float x) {
    float r;
    asm("ex2.approx.f32 %0, %1;" : "=f"(r) : "f"(x));
    return r;
}
__device__ __forceinline__ void cp_async16(void* smem_dst, const void* gmem_src) {
    unsigned saddr = (unsigned)__cvta_generic_to_shared(smem_dst);
    asm volatile("cp.async.ca.shared.global [%0], [%1], 16;\n"
                 :: "r"(saddr), "l"(gmem_src));
}

__global__ __launch_bounds__(TPB, 8) void dfine_lqe_kernel(
    const float* __restrict__ scores,   // (tokens, 80)
    const float* __restrict__ pc,       // (tokens, 132)
    const float* __restrict__ W1,       // (20, 64)
    const float* __restrict__ b1,       // (64,)
    const float* __restrict__ W2,       // (64, 1)
    const float* __restrict__ b2,       // (1,)
    float* __restrict__ out,            // (tokens, 80)
    int tokens)
{
    __shared__ __align__(16) float sPC[4 * 32 * RSTR];  // per-warp 32x13vec4 tiles (26624 B)
    __shared__ float sW1e[64 * 16];     // folded W1, [j][16] (uniform broadcast rows)
    __shared__ float sB1[64];
    __shared__ float sW2[64];
    __shared__ float sQ[TPB];

    const int tid = threadIdx.x;
    const int w   = tid >> 5;
    const int l   = tid & 31;
    const int t0  = blockIdx.x * TPB;
    const int ntb = min(TPB, tokens - t0);

    float* wbuf = &sPC[w * 32 * RSTR];
    const int wt0 = t0 + 32 * w;                        // warp's first token
    const int nrw = min(32, max(0, ntb - 32 * w));      // valid rows for this warp

    const float4* pc4 = reinterpret_cast<const float4*>(pc);

    // ---- stage weights (independent of streaming; synced once before MLP) ----
    #pragma unroll 2
    for (int i = tid; i < 1024; i += TPB) {
        int j = i >> 4;
        int d = i & 15;
        int g = d >> 2, k = d & 3;
        sW1e[i] = W1[(g * 5 + k) * 64 + j] + 0.25f * W1[(g * 5 + 4) * 64 + j];
    }
    if (tid < 64) {
        sB1[tid] = b1[tid];
        sW2[tid] = W2[tid];
    }

    // ---- running per-group top-4 (log2 domain) + unshifted 2^x sums ----
    float m0[4], m1[4], m2[4], m3[4], sum[4];
    #pragma unroll
    for (int g = 0; g < 4; g++) {
        m0[g] = NEG_INF; m1[g] = NEG_INF; m2[g] = NEG_INF; m3[g] = NEG_INF;
        sum[g] = 0.0f;
    }

    const float4* myrow = reinterpret_cast<const float4*>(&wbuf[l * RSTR]);

    // ---- 3 warp-local stages of 11 vec4s each (33 vec4 = full 132-float row) ----
    #pragma unroll
    for (int s = 0; s < 3; s++) {
        // coalesced cp.async: flat order over 32 rows x 11 vec4
        #pragma unroll
        for (int r = 0; r < 11; r++) {
            int i   = l + 32 * r;                       // 0..351
            int row = i / 11;
            int v   = i - row * 11;
            if (row < nrw)
                cp_async16(&wbuf[row * RSTR + 4 * v],
                           &pc4[(size_t)(wt0 + row) * 33 + 11 * s + v]);
        }
        asm volatile("cp.async.commit_group;\n");
        asm volatile("cp.async.wait_group 0;\n" ::: "memory");
        __syncwarp();

        if (l < nrw) {
            #pragma unroll
            for (int jj = 0; jj < 11; jj++) {
                float4 t = myrow[jj];
                #pragma unroll
                for (int e = 0; e < 4; e++) {
                    const int pos = 4 * (11 * s + jj) + e;   // compile-time
                    const int g   = pos / 33;                // compile-time group
                    float raw = (e == 0) ? t.x : (e == 1) ? t.y : (e == 2) ? t.z : t.w;
                    float val = raw * LOG2E;
                    float a1 = fminf(m0[g], val); m0[g] = fmaxf(m0[g], val);
                    float a2 = fminf(m1[g], a1);  m1[g] = fmaxf(m1[g], a1);
                    float a3 = fminf(m2[g], a2);  m2[g] = fmaxf(m2[g], a2);
                    m3[g] = fmaxf(m3[g], a3);
                    sum[g] += ex2(val);
                }
            }
        }
        __syncwarp();                                   // all lanes done before tile overwrite
    }

    __syncthreads();                                    // weights visible (one block barrier)

    if (tid < ntb) {
        // top-4 probabilities: p_k = 2^{m_k} / sum
        float stat[16];
        #pragma unroll
        for (int g = 0; g < 4; g++) {
            float inv = 1.0f / sum[g];
            stat[g * 4 + 0] = ex2(m0[g]) * inv;
            stat[g * 4 + 1] = ex2(m1[g]) * inv;
            stat[g * 4 + 2] = ex2(m2[g]) * inv;
            stat[g * 4 + 3] = ex2(m3[g]) * inv;
        }

        // ---- tiny MLP (mean folded): q = W2 . relu(W1e^T p + b1) + b2 ----
        float q = b2[0];
        #pragma unroll 4
        for (int j = 0; j < 64; j++) {
            const float4* w4 = reinterpret_cast<const float4*>(&sW1e[j * 16]);  // warp-uniform
            float acc = sB1[j];
            float4 wa = w4[0], wb = w4[1], wc = w4[2], wd = w4[3];
            acc = fmaf(stat[0],  wa.x, acc); acc = fmaf(stat[1],  wa.y, acc);
            acc = fmaf(stat[2],  wa.z, acc); acc = fmaf(stat[3],  wa.w, acc);
            acc = fmaf(stat[4],  wb.x, acc); acc = fmaf(stat[5],  wb.y, acc);
            acc = fmaf(stat[6],  wb.z, acc); acc = fmaf(stat[7],  wb.w, acc);
            acc = fmaf(stat[8],  wc.x, acc); acc = fmaf(stat[9],  wc.y, acc);
            acc = fmaf(stat[10], wc.z, acc); acc = fmaf(stat[11], wc.w, acc);
            acc = fmaf(stat[12], wd.x, acc); acc = fmaf(stat[13], wd.y, acc);
            acc = fmaf(stat[14], wd.z, acc); acc = fmaf(stat[15], wd.w, acc);
            q = fmaf(fmaxf(acc, 0.0f), sW2[j], q);
        }
        sQ[tid] = q;
    }
    __syncthreads();

    // ---- coalesced epilogue: out = scores + q[token], float4 ----
    {
        const float4* sc4  = reinterpret_cast<const float4*>(scores) + (size_t)t0 * 20;
        float4*       out4 = reinterpret_cast<float4*>(out) + (size_t)t0 * 20;
        const int nvec = ntb * 20;
        #pragma unroll 4
        for (int i = tid; i < nvec; i += TPB) {
            int row = i / 20;
            float4 s = sc4[i];
            float qq = sQ[row];
            s.x += qq; s.y += qq; s.z += qq; s.w += qq;
            out4[i] = s;
        }
    }
}

extern "C" void kernel_launch(void* const* d_in, const int* in_sizes, int n_in,
                              void* d_out, int out_size)
{
    const float* scores = (const float*)d_in[0];
    const float* pc     = (const float*)d_in[1];
    const float* W1     = (const float*)d_in[2];
    const float* b1     = (const float*)d_in[3];
    const float* W2     = (const float*)d_in[4];
    const float* b2     = (const float*)d_in[5];
    float* out = (float*)d_out;

    const int tokens = in_sizes[1] / 132;
    const int nblocks = (tokens + TPB - 1) / TPB;

    dfine_lqe_kernel<<<nblocks, TPB>>>(scores, pc, W1, b1, W2, b2, out, tokens);
}

// round 16
// speedup vs baseline: 1.6662x; 1.6662x over previous
#include <cuda_runtime.h>
#include <math.h>

#define TPB  128
#define TILE 256                // tokens per block (2 per thread)
#define NEG_INF (-3.402823466e+38f)
#define LOG2E 1.4426950408889634f

__device__ __forceinline__ float ex2(float x) {
    float r;
    asm("ex2.approx.f32 %0, %1;" : "=f"(r) : "f"(x));
    return r;
}

__global__ __launch_bounds__(TPB, 6) void dfine_lqe_kernel(
    const float* __restrict__ scores,   // (tokens, 80)
    const float* __restrict__ pc,       // (tokens, 132)
    const float* __restrict__ W1,       // (20, 64)
    const float* __restrict__ b1,       // (64,)
    const float* __restrict__ W2,       // (64, 1)
    const float* __restrict__ b2,       // (1,)
    float* __restrict__ out,            // (tokens, 80)
    int tokens)
{
    __shared__ float sW1e[64 * 16];     // folded W1, row-major [j][16] (uniform broadcast)
    __shared__ float sB1[64];
    __shared__ float sW2[64];
    __shared__ float sQ[TILE];

    const int tid = threadIdx.x;
    const int t0  = blockIdx.x * TILE;
    const int ntb = min(TILE, tokens - t0);

    // ---- stage effective weights: W1e[j][4g+k] = W1[5g+k][j] + 0.25*W1[5g+4][j] ----
    #pragma unroll 2
    for (int i = tid; i < 1024; i += TPB) {
        int j = i >> 4;
        int d = i & 15;
        int g = d >> 2, k = d & 3;
        sW1e[i] = W1[(g * 5 + k) * 64 + j] + 0.25f * W1[(g * 5 + 4) * 64 + j];
    }
    if (tid < 64) {
        sB1[tid] = b1[tid];
        sW2[tid] = W2[tid];
    }
    __syncthreads();

    // two tokens per thread (clamped so loads stay in-bounds; stores guarded)
    const int tokA = min(t0 + tid,       tokens - 1);
    const int tokB = min(t0 + tid + TPB, tokens - 1);
    const float4* pA = reinterpret_cast<const float4*>(pc) + (size_t)tokA * 33;
    const float4* pB = reinterpret_cast<const float4*>(pc) + (size_t)tokB * 33;

    // running top-4 (log2 domain) + unshifted 2^x sums, two independent streams
    float a0[4], a1r[4], a2r[4], a3r[4], sA[4];
    float c0[4], c1r[4], c2r[4], c3r[4], sB[4];
    #pragma unroll
    for (int g = 0; g < 4; g++) {
        a0[g] = a1r[g] = a2r[g] = a3r[g] = NEG_INF; sA[g] = 0.0f;
        c0[g] = c1r[g] = c2r[g] = c3r[g] = NEG_INF; sB[g] = 0.0f;
    }

    #pragma unroll
    for (int v = 0; v < 33; v++) {
        float4 ta = pA[v];
        float4 tb = pB[v];
        #pragma unroll
        for (int e = 0; e < 4; e++) {
            const int pos = 4 * v + e;
            const int g   = pos / 33;               // compile-time group id
            float va = ((e == 0) ? ta.x : (e == 1) ? ta.y : (e == 2) ? ta.z : ta.w) * LOG2E;
            float vb = ((e == 0) ? tb.x : (e == 1) ? tb.y : (e == 2) ? tb.z : tb.w) * LOG2E;
            // stream A insert
            float x1 = fminf(a0[g], va);  a0[g]  = fmaxf(a0[g], va);
            float x2 = fminf(a1r[g], x1); a1r[g] = fmaxf(a1r[g], x1);
            float x3 = fminf(a2r[g], x2); a2r[g] = fmaxf(a2r[g], x2);
            a3r[g] = fmaxf(a3r[g], x3);
            sA[g] += ex2(va);
            // stream B insert (independent chain)
            float y1 = fminf(c0[g], vb);  c0[g]  = fmaxf(c0[g], vb);
            float y2 = fminf(c1r[g], y1); c1r[g] = fmaxf(c1r[g], y1);
            float y3 = fminf(c2r[g], y2); c2r[g] = fmaxf(c2r[g], y2);
            c3r[g] = fmaxf(c3r[g], y3);
            sB[g] += ex2(vb);
        }
    }

    // top-4 probabilities for both tokens
    float statA[16], statB[16];
    #pragma unroll
    for (int g = 0; g < 4; g++) {
        float ia = 1.0f / sA[g];
        statA[g * 4 + 0] = ex2(a0[g])  * ia;
        statA[g * 4 + 1] = ex2(a1r[g]) * ia;
        statA[g * 4 + 2] = ex2(a2r[g]) * ia;
        statA[g * 4 + 3] = ex2(a3r[g]) * ia;
        float ib = 1.0f / sB[g];
        statB[g * 4 + 0] = ex2(c0[g])  * ib;
        statB[g * 4 + 1] = ex2(c1r[g]) * ib;
        statB[g * 4 + 2] = ex2(c2r[g]) * ib;
        statB[g * 4 + 3] = ex2(c3r[g]) * ib;
    }

    // ---- tiny MLP (mean folded), weights loaded once per j for BOTH tokens ----
    float qA = b2[0], qB = qA;
    #pragma unroll 4
    for (int j = 0; j < 64; j++) {
        const float4* w4 = reinterpret_cast<const float4*>(&sW1e[j * 16]);  // warp-uniform
        float bj = sB1[j];
        float4 wa = w4[0], wb = w4[1], wc = w4[2], wd = w4[3];
        float accA = bj, accB = bj;
        accA = fmaf(statA[0],  wa.x, accA); accB = fmaf(statB[0],  wa.x, accB);
        accA = fmaf(statA[1],  wa.y, accA); accB = fmaf(statB[1],  wa.y, accB);
        accA = fmaf(statA[2],  wa.z, accA); accB = fmaf(statB[2],  wa.z, accB);
        accA = fmaf(statA[3],  wa.w, accA); accB = fmaf(statB[3],  wa.w, accB);
        accA = fmaf(statA[4],  wb.x, accA); accB = fmaf(statB[4],  wb.x, accB);
        accA = fmaf(statA[5],  wb.y, accA); accB = fmaf(statB[5],  wb.y, accB);
        accA = fmaf(statA[6],  wb.z, accA); accB = fmaf(statB[6],  wb.z, accB);
        accA = fmaf(statA[7],  wb.w, accA); accB = fmaf(statB[7],  wb.w, accB);
        accA = fmaf(statA[8],  wc.x, accA); accB = fmaf(statB[8],  wc.x, accB);
        accA = fmaf(statA[9],  wc.y, accA); accB = fmaf(statB[9],  wc.y, accB);
        accA = fmaf(statA[10], wc.z, accA); accB = fmaf(statB[10], wc.z, accB);
        accA = fmaf(statA[11], wc.w, accA); accB = fmaf(statB[11], wc.w, accB);
        accA = fmaf(statA[12], wd.x, accA); accB = fmaf(statB[12], wd.x, accB);
        accA = fmaf(statA[13], wd.y, accA); accB = fmaf(statB[13], wd.y, accB);
        accA = fmaf(statA[14], wd.z, accA); accB = fmaf(statB[14], wd.z, accB);
        accA = fmaf(statA[15], wd.w, accA); accB = fmaf(statB[15], wd.w, accB);
        float w2j = sW2[j];
        qA = fmaf(fmaxf(accA, 0.0f), w2j, qA);
        qB = fmaf(fmaxf(accB, 0.0f), w2j, qB);
    }
    sQ[tid]       = qA;
    sQ[tid + TPB] = qB;
    __syncthreads();

    // ---- coalesced epilogue: out = scores + q[token], float4 ----
    {
        const float4* sc4  = reinterpret_cast<const float4*>(scores) + (size_t)t0 * 20;
        float4*       out4 = reinterpret_cast<float4*>(out) + (size_t)t0 * 20;
        const int nvec = ntb * 20;
        #pragma unroll 4
        for (int i = tid; i < nvec; i += TPB) {
            int row = i / 20;
            float4 s = sc4[i];
            float qq = sQ[row];
            s.x += qq; s.y += qq; s.z += qq; s.w += qq;
            out4[i] = s;
        }
    }
}

extern "C" void kernel_launch(void* const* d_in, const int* in_sizes, int n_in,
                              void* d_out, int out_size)
{
    const float* scores = (const float*)d_in[0];
    const float* pc     = (const float*)d_in[1];
    const float* W1     = (const float*)d_in[2];
    const float* b1     = (const float*)d_in[3];
    const float* W2     = (const float*)d_in[4];
    const float* b2     = (const float*)d_in[5];
    float* out = (float*)d_out;

    const int tokens = in_sizes[1] / 132;
    const int nblocks = (tokens + TILE - 1) / TILE;

    dfine_lqe_kernel<<<nblocks, TPB>>>(scores, pc, W1, b1, W2, b2, out, tokens);
}